// round 3
// baseline (speedup 1.0000x reference)
#include <cuda_runtime.h>
#include <cuda_bf16.h>

#define NODE_DIM 64
#define EDGE_DIM 32
#define HIDDEN   128
#define MAXN     100000
#define MAXE     800000
#define LN_EPS   1e-5f

// ---------------- scratch (no allocs allowed) ----------------
__device__ __align__(16) float g_xs[MAXN * HIDDEN];   // x @ W_src
__device__ __align__(16) float g_xd[MAXN * HIDDEN];   // x @ W_dst
__device__ __align__(16) float g_S [MAXN * HIDDEN];   // scatter-sum of edge activations
__device__ __align__(16) float g_deg[MAXN];           // in-degree (float)
__device__ __align__(16) float g_Wf[HIDDEN * HIDDEN]; // W_msg2 @ W_upd1[64:192]
__device__ __align__(16) float g_c [HIDDEN];          // b_msg2 @ W_upd1[64:192]

__device__ __forceinline__ float warp_sum(float v) {
#pragma unroll
    for (int o = 16; o > 0; o >>= 1) v += __shfl_xor_sync(0xffffffffu, v, o);
    return v;
}

__device__ __forceinline__ float silu_f(float y) {
    return y * (1.0f / (1.0f + __expf(-y)));
}

__device__ __forceinline__ void red_add_v4(float* p, float4 v) {
    asm volatile("red.global.add.v4.f32 [%0], {%1,%2,%3,%4};"
                 :: "l"(p), "f"(v.x), "f"(v.y), "f"(v.z), "f"(v.w) : "memory");
}

// ---------------- K0: fold W_msg2 through W_upd1 (agg part) ----------------
__global__ void k_fuse(const float* __restrict__ Wmsg2,
                       const float* __restrict__ Wupd1,
                       const float* __restrict__ bmsg2) {
    int k = blockIdx.x;      // 0..127
    int t = threadIdx.x;     // 0..127
    float acc = 0.f;
#pragma unroll 8
    for (int j = 0; j < HIDDEN; ++j)
        acc = fmaf(Wmsg2[k * HIDDEN + j], Wupd1[(NODE_DIM + j) * HIDDEN + t], acc);
    g_Wf[k * HIDDEN + t] = acc;
    if (k == 0) {
        float c = 0.f;
#pragma unroll 8
        for (int j = 0; j < HIDDEN; ++j)
            c = fmaf(bmsg2[j], Wupd1[(NODE_DIM + j) * HIDDEN + t], c);
        g_c[t] = c;
    }
}

// ---------------- K1: xs = x@W_src, xd = x@W_dst (warp per node) ----------------
__global__ __launch_bounds__(256)
void k_node_proj(const float* __restrict__ x,
                 const float* __restrict__ Wmsg1, int N) {
    extern __shared__ float sW[]; // 128 x 128 (rows 0..127 of W_msg1)
    {
        const float4* src = (const float4*)Wmsg1;
        float4* dst = (float4*)sW;
        for (int i = threadIdx.x; i < HIDDEN * HIDDEN / 4; i += blockDim.x) dst[i] = src[i];
    }
    __syncthreads();
    const int lane = threadIdx.x & 31, warp = threadIdx.x >> 5;
    const int wpb = blockDim.x >> 5;
    for (int n = blockIdx.x * wpb + warp; n < N; n += gridDim.x * wpb) {
        float x0 = x[n * NODE_DIM + lane * 2];
        float x1 = x[n * NODE_DIM + lane * 2 + 1];
        float4 as = make_float4(0.f, 0.f, 0.f, 0.f);
        float4 ad = make_float4(0.f, 0.f, 0.f, 0.f);
#pragma unroll
        for (int c = 0; c < 32; ++c) {
            float a0 = __shfl_sync(0xffffffffu, x0, c);
            float a1 = __shfl_sync(0xffffffffu, x1, c);
            const float4 w0 = *(const float4*)&sW[(2 * c)     * HIDDEN + lane * 4];
            const float4 w1 = *(const float4*)&sW[(2 * c + 1) * HIDDEN + lane * 4];
            const float4 v0 = *(const float4*)&sW[(64 + 2 * c)     * HIDDEN + lane * 4];
            const float4 v1 = *(const float4*)&sW[(64 + 2 * c + 1) * HIDDEN + lane * 4];
            as.x = fmaf(a0, w0.x, fmaf(a1, w1.x, as.x));
            as.y = fmaf(a0, w0.y, fmaf(a1, w1.y, as.y));
            as.z = fmaf(a0, w0.z, fmaf(a1, w1.z, as.z));
            as.w = fmaf(a0, w0.w, fmaf(a1, w1.w, as.w));
            ad.x = fmaf(a0, v0.x, fmaf(a1, v1.x, ad.x));
            ad.y = fmaf(a0, v0.y, fmaf(a1, v1.y, ad.y));
            ad.z = fmaf(a0, v0.z, fmaf(a1, v1.z, ad.z));
            ad.w = fmaf(a0, v0.w, fmaf(a1, v1.w, ad.w));
        }
        *(float4*)&g_xs[n * HIDDEN + lane * 4] = as;
        *(float4*)&g_xd[n * HIDDEN + lane * 4] = ad;
    }
}

// ---------------- K2: edge kernel (warp per edge) ----------------
__global__ __launch_bounds__(256)
void k_edge(const int* __restrict__ ei, const float* __restrict__ ea,
            const float* __restrict__ Wmsg1, const float* __restrict__ b1,
            const float* __restrict__ gm, const float* __restrict__ bem, int E) {
    __shared__ __align__(16) float sWe[EDGE_DIM * HIDDEN]; // rows 128..159 of W_msg1
    __shared__ __align__(16) float sb[HIDDEN];
    __shared__ __align__(16) float sg[HIDDEN];
    __shared__ __align__(16) float sbe[HIDDEN];
    for (int i = threadIdx.x; i < EDGE_DIM * HIDDEN; i += blockDim.x)
        sWe[i] = Wmsg1[HIDDEN * HIDDEN + i];
    for (int i = threadIdx.x; i < HIDDEN; i += blockDim.x) {
        sb[i] = b1[i]; sg[i] = gm[i]; sbe[i] = bem[i];
    }
    __syncthreads();
    const int lane = threadIdx.x & 31, warp = threadIdx.x >> 5;
    const int wpb = blockDim.x >> 5;
    for (int e = blockIdx.x * wpb + warp; e < E; e += gridDim.x * wpb) {
        const int src = ei[e];
        const int dst = ei[E + e];
        float4 acc = *(const float4*)&g_xs[(size_t)src * HIDDEN + lane * 4];
        const float4 vd = *(const float4*)&g_xd[(size_t)dst * HIDDEN + lane * 4];
        const float4 bb = *(const float4*)&sb[lane * 4];
        acc.x += vd.x + bb.x; acc.y += vd.y + bb.y;
        acc.z += vd.z + bb.z; acc.w += vd.w + bb.w;
        const float eav = ea[(size_t)e * EDGE_DIM + lane];
#pragma unroll
        for (int k = 0; k < 32; ++k) {
            const float a = __shfl_sync(0xffffffffu, eav, k);
            const float4 w = *(const float4*)&sWe[k * HIDDEN + lane * 4];
            acc.x = fmaf(a, w.x, acc.x);
            acc.y = fmaf(a, w.y, acc.y);
            acc.z = fmaf(a, w.z, acc.z);
            acc.w = fmaf(a, w.w, acc.w);
        }
        // LayerNorm over 128 (warp)
        float s = warp_sum(acc.x + acc.y + acc.z + acc.w);
        const float mu = s * (1.0f / HIDDEN);
        const float dx = acc.x - mu, dy = acc.y - mu, dz = acc.z - mu, dw = acc.w - mu;
        float ss = warp_sum(dx * dx + dy * dy + dz * dz + dw * dw);
        const float rstd = rsqrtf(ss * (1.0f / HIDDEN) + LN_EPS);
        const float4 gv  = *(const float4*)&sg[lane * 4];
        const float4 bev = *(const float4*)&sbe[lane * 4];
        float4 act;
        act.x = silu_f(dx * rstd * gv.x + bev.x);
        act.y = silu_f(dy * rstd * gv.y + bev.y);
        act.z = silu_f(dz * rstd * gv.z + bev.z);
        act.w = silu_f(dw * rstd * gv.w + bev.w);
        red_add_v4(&g_S[(size_t)dst * HIDDEN + lane * 4], act);
        if (lane == 0) atomicAdd(&g_deg[dst], 1.0f);
    }
}

// ---------------- K3: fused node update (warp per node) ----------------
__global__ __launch_bounds__(512, 1)
void k_update(const float* __restrict__ x,
              const float* __restrict__ Wupd1, const float* __restrict__ bupd1,
              const float* __restrict__ gu, const float* __restrict__ beu,
              const float* __restrict__ Wupd2, const float* __restrict__ bupd2,
              float* __restrict__ out, int N) {
    extern __shared__ float sm[];
    float* sWa = sm;                       // 64*128
    float* sWf = sWa + NODE_DIM * HIDDEN;  // 128*128
    float* sW2 = sWf + HIDDEN * HIDDEN;    // 128*64
    float* sb1 = sW2 + HIDDEN * NODE_DIM;  // 128
    float* sc  = sb1 + HIDDEN;             // 128
    float* sg  = sc  + HIDDEN;             // 128
    float* sbe = sg  + HIDDEN;             // 128
    float* sb2 = sbe + HIDDEN;             // 64
    for (int i = threadIdx.x; i < NODE_DIM * HIDDEN; i += blockDim.x) sWa[i] = Wupd1[i];
    for (int i = threadIdx.x; i < HIDDEN * HIDDEN; i += blockDim.x)   sWf[i] = g_Wf[i];
    for (int i = threadIdx.x; i < HIDDEN * NODE_DIM; i += blockDim.x) sW2[i] = Wupd2[i];
    for (int i = threadIdx.x; i < HIDDEN; i += blockDim.x) {
        sb1[i] = bupd1[i]; sc[i] = g_c[i]; sg[i] = gu[i]; sbe[i] = beu[i];
    }
    for (int i = threadIdx.x; i < NODE_DIM; i += blockDim.x) sb2[i] = bupd2[i];
    __syncthreads();

    const int lane = threadIdx.x & 31, warp = threadIdx.x >> 5;
    const int wpb = blockDim.x >> 5;
    for (int n = blockIdx.x * wpb + warp; n < N; n += gridDim.x * wpb) {
        const float x0 = x[n * NODE_DIM + lane * 2];
        const float x1 = x[n * NODE_DIM + lane * 2 + 1];
        const float4 s4 = *(const float4*)&g_S[(size_t)n * HIDDEN + lane * 4];
        const float dg = g_deg[n];
        float4 acc;
        acc.x = sb1[lane * 4 + 0] + dg * sc[lane * 4 + 0];
        acc.y = sb1[lane * 4 + 1] + dg * sc[lane * 4 + 1];
        acc.z = sb1[lane * 4 + 2] + dg * sc[lane * 4 + 2];
        acc.w = sb1[lane * 4 + 3] + dg * sc[lane * 4 + 3];
        // x @ W_upd1[0:64]
#pragma unroll
        for (int c = 0; c < 32; ++c) {
            const float a0 = __shfl_sync(0xffffffffu, x0, c);
            const float a1 = __shfl_sync(0xffffffffu, x1, c);
            const float4 w0 = *(const float4*)&sWa[(2 * c)     * HIDDEN + lane * 4];
            const float4 w1 = *(const float4*)&sWa[(2 * c + 1) * HIDDEN + lane * 4];
            acc.x = fmaf(a0, w0.x, fmaf(a1, w1.x, acc.x));
            acc.y = fmaf(a0, w0.y, fmaf(a1, w1.y, acc.y));
            acc.z = fmaf(a0, w0.z, fmaf(a1, w1.z, acc.z));
            acc.w = fmaf(a0, w0.w, fmaf(a1, w1.w, acc.w));
        }
        // S @ Wf
#pragma unroll
        for (int c = 0; c < 32; ++c) {
            const float v0 = __shfl_sync(0xffffffffu, s4.x, c);
            const float v1 = __shfl_sync(0xffffffffu, s4.y, c);
            const float v2 = __shfl_sync(0xffffffffu, s4.z, c);
            const float v3 = __shfl_sync(0xffffffffu, s4.w, c);
            const float4 wa = *(const float4*)&sWf[(4 * c + 0) * HIDDEN + lane * 4];
            const float4 wb = *(const float4*)&sWf[(4 * c + 1) * HIDDEN + lane * 4];
            const float4 wc = *(const float4*)&sWf[(4 * c + 2) * HIDDEN + lane * 4];
            const float4 wd = *(const float4*)&sWf[(4 * c + 3) * HIDDEN + lane * 4];
            acc.x = fmaf(v0, wa.x, fmaf(v1, wb.x, fmaf(v2, wc.x, fmaf(v3, wd.x, acc.x))));
            acc.y = fmaf(v0, wa.y, fmaf(v1, wb.y, fmaf(v2, wc.y, fmaf(v3, wd.y, acc.y))));
            acc.z = fmaf(v0, wa.z, fmaf(v1, wb.z, fmaf(v2, wc.z, fmaf(v3, wd.z, acc.z))));
            acc.w = fmaf(v0, wa.w, fmaf(v1, wb.w, fmaf(v2, wc.w, fmaf(v3, wd.w, acc.w))));
        }
        // LayerNorm + SiLU
        float s = warp_sum(acc.x + acc.y + acc.z + acc.w);
        const float mu = s * (1.0f / HIDDEN);
        const float dx = acc.x - mu, dy = acc.y - mu, dz = acc.z - mu, dw = acc.w - mu;
        float ss = warp_sum(dx * dx + dy * dy + dz * dz + dw * dw);
        const float rstd = rsqrtf(ss * (1.0f / HIDDEN) + LN_EPS);
        float4 act;
        act.x = silu_f(dx * rstd * sg[lane * 4 + 0] + sbe[lane * 4 + 0]);
        act.y = silu_f(dy * rstd * sg[lane * 4 + 1] + sbe[lane * 4 + 1]);
        act.z = silu_f(dz * rstd * sg[lane * 4 + 2] + sbe[lane * 4 + 2]);
        act.w = silu_f(dw * rstd * sg[lane * 4 + 3] + sbe[lane * 4 + 3]);
        // act @ W_upd2 (128 -> 64), each lane owns 2 output cols
        float o0 = 0.f, o1 = 0.f;
#pragma unroll
        for (int c = 0; c < 32; ++c) {
            const float a0 = __shfl_sync(0xffffffffu, act.x, c);
            const float a1 = __shfl_sync(0xffffffffu, act.y, c);
            const float a2 = __shfl_sync(0xffffffffu, act.z, c);
            const float a3 = __shfl_sync(0xffffffffu, act.w, c);
            const float2 w0 = *(const float2*)&sW2[(4 * c + 0) * NODE_DIM + lane * 2];
            const float2 w1 = *(const float2*)&sW2[(4 * c + 1) * NODE_DIM + lane * 2];
            const float2 w2 = *(const float2*)&sW2[(4 * c + 2) * NODE_DIM + lane * 2];
            const float2 w3 = *(const float2*)&sW2[(4 * c + 3) * NODE_DIM + lane * 2];
            o0 = fmaf(a0, w0.x, fmaf(a1, w1.x, fmaf(a2, w2.x, fmaf(a3, w3.x, o0))));
            o1 = fmaf(a0, w0.y, fmaf(a1, w1.y, fmaf(a2, w2.y, fmaf(a3, w3.y, o1))));
        }
        float2 res;
        res.x = x0 + o0 + sb2[lane * 2 + 0];
        res.y = x1 + o1 + sb2[lane * 2 + 1];
        *(float2*)&out[(size_t)n * NODE_DIM + lane * 2] = res;
    }
}

// ---------------- host ----------------
extern "C" void kernel_launch(void* const* d_in, const int* in_sizes, int n_in,
                              void* d_out, int out_size) {
    const float* x      = (const float*)d_in[0];
    const int*   ei     = (const int*)  d_in[1];
    const float* ea     = (const float*)d_in[2];
    const float* Wmsg1  = (const float*)d_in[3];
    const float* bmsg1  = (const float*)d_in[4];
    const float* gmsg   = (const float*)d_in[5];
    const float* bemsg  = (const float*)d_in[6];
    const float* Wmsg2  = (const float*)d_in[7];
    const float* bmsg2  = (const float*)d_in[8];
    const float* Wupd1  = (const float*)d_in[9];
    const float* bupd1  = (const float*)d_in[10];
    const float* gupd   = (const float*)d_in[11];
    const float* beupd  = (const float*)d_in[12];
    const float* Wupd2  = (const float*)d_in[13];
    const float* bupd2  = (const float*)d_in[14];
    float* out = (float*)d_out;

    const int N = in_sizes[0] / NODE_DIM;
    const int E = in_sizes[2] / EDGE_DIM;

    void *pS = nullptr, *pdeg = nullptr;
    cudaGetSymbolAddress(&pS, g_S);
    cudaGetSymbolAddress(&pdeg, g_deg);
    cudaMemsetAsync(pS, 0, (size_t)N * HIDDEN * sizeof(float), 0);
    cudaMemsetAsync(pdeg, 0, (size_t)N * sizeof(float), 0);

    const int smem_proj = HIDDEN * HIDDEN * sizeof(float);                 // 64 KB
    const int smem_upd  = (NODE_DIM * HIDDEN + HIDDEN * HIDDEN +
                           HIDDEN * NODE_DIM + 4 * HIDDEN + NODE_DIM) * sizeof(float); // ~130 KB
    cudaFuncSetAttribute(k_node_proj, cudaFuncAttributeMaxDynamicSharedMemorySize, smem_proj);
    cudaFuncSetAttribute(k_update,    cudaFuncAttributeMaxDynamicSharedMemorySize, smem_upd);

    k_fuse<<<HIDDEN, HIDDEN>>>(Wmsg2, Wupd1, bmsg2);
    k_node_proj<<<444, 256, smem_proj>>>(x, Wmsg1, N);
    k_edge<<<1184, 256>>>(ei, ea, Wmsg1, bmsg1, gmsg, bemsg, E);
    k_update<<<148, 512, smem_upd>>>(x, Wupd1, bupd1, gupd, beupd, Wupd2, bupd2, out, N);
}

// round 4
// speedup vs baseline: 1.7765x; 1.7765x over previous
#include <cuda_runtime.h>
#include <cuda_bf16.h>

#define NODE_DIM 64
#define EDGE_DIM 32
#define HIDDEN   128
#define MAXN     100000
#define MAXE     800000
#define LN_EPS   1e-5f

// ---------------- scratch (no allocs allowed) ----------------
__device__ __align__(16) float g_xs[MAXN * HIDDEN];   // x @ W_src
__device__ __align__(16) float g_xd[MAXN * HIDDEN];   // x @ W_dst
__device__ __align__(16) float g_S [MAXN * HIDDEN];   // scatter-sum of edge activations
__device__ __align__(16) float g_deg[MAXN];           // in-degree (float)
__device__ __align__(16) float g_Wf[HIDDEN * HIDDEN]; // W_msg2 @ W_upd1[64:192]
__device__ __align__(16) float g_c [HIDDEN];          // b_msg2 @ W_upd1[64:192]

__device__ __forceinline__ float warp_sum(float v) {
#pragma unroll
    for (int o = 16; o > 0; o >>= 1) v += __shfl_xor_sync(0xffffffffu, v, o);
    return v;
}

__device__ __forceinline__ float silu_f(float y) {
    return y * (1.0f / (1.0f + __expf(-y)));
}

__device__ __forceinline__ void red_add_v4(float* p, float4 v) {
    asm volatile("red.global.add.v4.f32 [%0], {%1,%2,%3,%4};"
                 :: "l"(p), "f"(v.x), "f"(v.y), "f"(v.z), "f"(v.w) : "memory");
}

// ---------------- K0: fold W_msg2 through W_upd1 (agg part) ----------------
__global__ void k_fuse(const float* __restrict__ Wmsg2,
                       const float* __restrict__ Wupd1,
                       const float* __restrict__ bmsg2) {
    int k = blockIdx.x;      // 0..127
    int t = threadIdx.x;     // 0..127
    float acc = 0.f;
#pragma unroll 8
    for (int j = 0; j < HIDDEN; ++j)
        acc = fmaf(Wmsg2[k * HIDDEN + j], Wupd1[(NODE_DIM + j) * HIDDEN + t], acc);
    g_Wf[k * HIDDEN + t] = acc;
    if (k == 0) {
        float c = 0.f;
#pragma unroll 8
        for (int j = 0; j < HIDDEN; ++j)
            c = fmaf(bmsg2[j], Wupd1[(NODE_DIM + j) * HIDDEN + t], c);
        g_c[t] = c;
    }
}

// ---------------- K1: xs = x@W_src, xd = x@W_dst (warp per 4 nodes) ----------------
__global__ __launch_bounds__(256)
void k_node_proj(const float* __restrict__ x,
                 const float* __restrict__ Wmsg1, int N) {
    extern __shared__ float sW[]; // 128 x 128 (rows 0..127 of W_msg1)
    {
        const float4* src = (const float4*)Wmsg1;
        float4* dst = (float4*)sW;
        for (int i = threadIdx.x; i < HIDDEN * HIDDEN / 4; i += blockDim.x) dst[i] = src[i];
    }
    __syncthreads();
    const int lane = threadIdx.x & 31, warp = threadIdx.x >> 5;
    const int wpb = blockDim.x >> 5;
    const int gw = blockIdx.x * wpb + warp;
    const int nwarps = gridDim.x * wpb;
    for (int base = gw * 4; base < N; base += nwarps * 4) {
        float x0[4], x1[4];
#pragma unroll
        for (int j = 0; j < 4; ++j) {
            const int n = base + j;
            if (n < N) {
                x0[j] = x[n * NODE_DIM + lane * 2];
                x1[j] = x[n * NODE_DIM + lane * 2 + 1];
            } else { x0[j] = 0.f; x1[j] = 0.f; }
        }
        float4 as[4], ad[4];
#pragma unroll
        for (int j = 0; j < 4; ++j) {
            as[j] = make_float4(0.f, 0.f, 0.f, 0.f);
            ad[j] = make_float4(0.f, 0.f, 0.f, 0.f);
        }
#pragma unroll
        for (int c = 0; c < 32; ++c) {
            const float4 w0 = *(const float4*)&sW[(2 * c)     * HIDDEN + lane * 4];
            const float4 w1 = *(const float4*)&sW[(2 * c + 1) * HIDDEN + lane * 4];
            const float4 v0 = *(const float4*)&sW[(64 + 2 * c)     * HIDDEN + lane * 4];
            const float4 v1 = *(const float4*)&sW[(64 + 2 * c + 1) * HIDDEN + lane * 4];
#pragma unroll
            for (int j = 0; j < 4; ++j) {
                const float a0 = __shfl_sync(0xffffffffu, x0[j], c);
                const float a1 = __shfl_sync(0xffffffffu, x1[j], c);
                as[j].x = fmaf(a0, w0.x, fmaf(a1, w1.x, as[j].x));
                as[j].y = fmaf(a0, w0.y, fmaf(a1, w1.y, as[j].y));
                as[j].z = fmaf(a0, w0.z, fmaf(a1, w1.z, as[j].z));
                as[j].w = fmaf(a0, w0.w, fmaf(a1, w1.w, as[j].w));
                ad[j].x = fmaf(a0, v0.x, fmaf(a1, v1.x, ad[j].x));
                ad[j].y = fmaf(a0, v0.y, fmaf(a1, v1.y, ad[j].y));
                ad[j].z = fmaf(a0, v0.z, fmaf(a1, v1.z, ad[j].z));
                ad[j].w = fmaf(a0, v0.w, fmaf(a1, v1.w, ad[j].w));
            }
        }
#pragma unroll
        for (int j = 0; j < 4; ++j) {
            const int n = base + j;
            if (n < N) {
                *(float4*)&g_xs[(size_t)n * HIDDEN + lane * 4] = as[j];
                *(float4*)&g_xd[(size_t)n * HIDDEN + lane * 4] = ad[j];
            }
        }
    }
}

// ---------------- K2: edge kernel (warp per 4 edges) ----------------
__global__ __launch_bounds__(256)
void k_edge(const int* __restrict__ ei, const float* __restrict__ ea,
            const float* __restrict__ Wmsg1, const float* __restrict__ b1,
            const float* __restrict__ gm, const float* __restrict__ bem, int E) {
    __shared__ __align__(16) float sWe[EDGE_DIM * HIDDEN]; // rows 128..159 of W_msg1
    __shared__ __align__(16) float sb[HIDDEN];
    __shared__ __align__(16) float sg[HIDDEN];
    __shared__ __align__(16) float sbe[HIDDEN];
    for (int i = threadIdx.x; i < EDGE_DIM * HIDDEN; i += blockDim.x)
        sWe[i] = Wmsg1[HIDDEN * HIDDEN + i];
    for (int i = threadIdx.x; i < HIDDEN; i += blockDim.x) {
        sb[i] = b1[i]; sg[i] = gm[i]; sbe[i] = bem[i];
    }
    __syncthreads();
    const int lane = threadIdx.x & 31, warp = threadIdx.x >> 5;
    const int wpb = blockDim.x >> 5;
    const int gw = blockIdx.x * wpb + warp;
    const int nwarps = gridDim.x * wpb;
    const float4 bb  = *(const float4*)&sb[lane * 4];
    const float4 gv  = *(const float4*)&sg[lane * 4];
    const float4 bev = *(const float4*)&sbe[lane * 4];

    for (int base = gw * 4; base < E; base += nwarps * 4) {
        int dsts[4];
        float eav[4];
        float4 acc[4];
#pragma unroll
        for (int j = 0; j < 4; ++j) {
            const int e = base + j;
            if (e < E) {
                const int src = ei[e];
                dsts[j] = ei[E + e];
                const float4 vs = *(const float4*)&g_xs[(size_t)src * HIDDEN + lane * 4];
                const float4 vd = *(const float4*)&g_xd[(size_t)dsts[j] * HIDDEN + lane * 4];
                acc[j].x = vs.x + vd.x + bb.x;
                acc[j].y = vs.y + vd.y + bb.y;
                acc[j].z = vs.z + vd.z + bb.z;
                acc[j].w = vs.w + vd.w + bb.w;
                eav[j] = ea[(size_t)e * EDGE_DIM + lane];
            } else {
                dsts[j] = -1;
                acc[j] = make_float4(0.f, 0.f, 0.f, 0.f);
                eav[j] = 0.f;
            }
        }
#pragma unroll
        for (int k = 0; k < 32; ++k) {
            const float4 w = *(const float4*)&sWe[k * HIDDEN + lane * 4];
#pragma unroll
            for (int j = 0; j < 4; ++j) {
                const float a = __shfl_sync(0xffffffffu, eav[j], k);
                acc[j].x = fmaf(a, w.x, acc[j].x);
                acc[j].y = fmaf(a, w.y, acc[j].y);
                acc[j].z = fmaf(a, w.z, acc[j].z);
                acc[j].w = fmaf(a, w.w, acc[j].w);
            }
        }
#pragma unroll
        for (int j = 0; j < 4; ++j) {
            if (dsts[j] < 0) continue;
            float s = warp_sum(acc[j].x + acc[j].y + acc[j].z + acc[j].w);
            const float mu = s * (1.0f / HIDDEN);
            const float dx = acc[j].x - mu, dy = acc[j].y - mu;
            const float dz = acc[j].z - mu, dw = acc[j].w - mu;
            float ss = warp_sum(dx * dx + dy * dy + dz * dz + dw * dw);
            const float rstd = rsqrtf(ss * (1.0f / HIDDEN) + LN_EPS);
            float4 act;
            act.x = silu_f(dx * rstd * gv.x + bev.x);
            act.y = silu_f(dy * rstd * gv.y + bev.y);
            act.z = silu_f(dz * rstd * gv.z + bev.z);
            act.w = silu_f(dw * rstd * gv.w + bev.w);
            red_add_v4(&g_S[(size_t)dsts[j] * HIDDEN + lane * 4], act);
            if (lane == 0) atomicAdd(&g_deg[dsts[j]], 1.0f);
        }
    }
}

// ---------------- K3: fused node update (warp per 4 nodes) ----------------
__global__ __launch_bounds__(256, 1)
void k_update(const float* __restrict__ x,
              const float* __restrict__ Wupd1, const float* __restrict__ bupd1,
              const float* __restrict__ gu, const float* __restrict__ beu,
              const float* __restrict__ Wupd2, const float* __restrict__ bupd2,
              float* __restrict__ out, int N) {
    extern __shared__ float sm[];
    float* sWa = sm;                       // 64*128
    float* sWf = sWa + NODE_DIM * HIDDEN;  // 128*128
    float* sW2 = sWf + HIDDEN * HIDDEN;    // 128*64
    float* sb1 = sW2 + HIDDEN * NODE_DIM;  // 128
    float* sc  = sb1 + HIDDEN;             // 128
    float* sg  = sc  + HIDDEN;             // 128
    float* sbe = sg  + HIDDEN;             // 128
    float* sb2 = sbe + HIDDEN;             // 64
    for (int i = threadIdx.x; i < NODE_DIM * HIDDEN; i += blockDim.x) sWa[i] = Wupd1[i];
    for (int i = threadIdx.x; i < HIDDEN * HIDDEN; i += blockDim.x)   sWf[i] = g_Wf[i];
    for (int i = threadIdx.x; i < HIDDEN * NODE_DIM; i += blockDim.x) sW2[i] = Wupd2[i];
    for (int i = threadIdx.x; i < HIDDEN; i += blockDim.x) {
        sb1[i] = bupd1[i]; sc[i] = g_c[i]; sg[i] = gu[i]; sbe[i] = beu[i];
    }
    for (int i = threadIdx.x; i < NODE_DIM; i += blockDim.x) sb2[i] = bupd2[i];
    __syncthreads();

    const int lane = threadIdx.x & 31, warp = threadIdx.x >> 5;
    const int wpb = blockDim.x >> 5;
    const int gw = blockIdx.x * wpb + warp;
    const int nwarps = gridDim.x * wpb;

    const float4 b1v = *(const float4*)&sb1[lane * 4];
    const float4 cv  = *(const float4*)&sc [lane * 4];
    const float4 gv  = *(const float4*)&sg [lane * 4];
    const float4 bev = *(const float4*)&sbe[lane * 4];
    const float2 b2v = *(const float2*)&sb2[lane * 2];

    for (int base = gw * 4; base < N; base += nwarps * 4) {
        float x0[4], x1[4];
        float4 s4[4], acc[4];
#pragma unroll
        for (int j = 0; j < 4; ++j) {
            const int n = base + j;
            if (n < N) {
                x0[j] = x[n * NODE_DIM + lane * 2];
                x1[j] = x[n * NODE_DIM + lane * 2 + 1];
                s4[j] = *(const float4*)&g_S[(size_t)n * HIDDEN + lane * 4];
                const float dg = g_deg[n];
                acc[j].x = b1v.x + dg * cv.x;
                acc[j].y = b1v.y + dg * cv.y;
                acc[j].z = b1v.z + dg * cv.z;
                acc[j].w = b1v.w + dg * cv.w;
            } else {
                x0[j] = x1[j] = 0.f;
                s4[j] = make_float4(0.f, 0.f, 0.f, 0.f);
                acc[j] = make_float4(0.f, 0.f, 0.f, 0.f);
            }
        }
        // x @ W_upd1[0:64]
#pragma unroll
        for (int c = 0; c < 32; ++c) {
            const float4 w0 = *(const float4*)&sWa[(2 * c)     * HIDDEN + lane * 4];
            const float4 w1 = *(const float4*)&sWa[(2 * c + 1) * HIDDEN + lane * 4];
#pragma unroll
            for (int j = 0; j < 4; ++j) {
                const float a0 = __shfl_sync(0xffffffffu, x0[j], c);
                const float a1 = __shfl_sync(0xffffffffu, x1[j], c);
                acc[j].x = fmaf(a0, w0.x, fmaf(a1, w1.x, acc[j].x));
                acc[j].y = fmaf(a0, w0.y, fmaf(a1, w1.y, acc[j].y));
                acc[j].z = fmaf(a0, w0.z, fmaf(a1, w1.z, acc[j].z));
                acc[j].w = fmaf(a0, w0.w, fmaf(a1, w1.w, acc[j].w));
            }
        }
        // S @ Wf
#pragma unroll
        for (int c = 0; c < 32; ++c) {
            const float4 wa = *(const float4*)&sWf[(4 * c + 0) * HIDDEN + lane * 4];
            const float4 wb = *(const float4*)&sWf[(4 * c + 1) * HIDDEN + lane * 4];
            const float4 wc = *(const float4*)&sWf[(4 * c + 2) * HIDDEN + lane * 4];
            const float4 wd = *(const float4*)&sWf[(4 * c + 3) * HIDDEN + lane * 4];
#pragma unroll
            for (int j = 0; j < 4; ++j) {
                const float v0 = __shfl_sync(0xffffffffu, s4[j].x, c);
                const float v1 = __shfl_sync(0xffffffffu, s4[j].y, c);
                const float v2 = __shfl_sync(0xffffffffu, s4[j].z, c);
                const float v3 = __shfl_sync(0xffffffffu, s4[j].w, c);
                acc[j].x = fmaf(v0, wa.x, fmaf(v1, wb.x, fmaf(v2, wc.x, fmaf(v3, wd.x, acc[j].x))));
                acc[j].y = fmaf(v0, wa.y, fmaf(v1, wb.y, fmaf(v2, wc.y, fmaf(v3, wd.y, acc[j].y))));
                acc[j].z = fmaf(v0, wa.z, fmaf(v1, wb.z, fmaf(v2, wc.z, fmaf(v3, wd.z, acc[j].z))));
                acc[j].w = fmaf(v0, wa.w, fmaf(v1, wb.w, fmaf(v2, wc.w, fmaf(v3, wd.w, acc[j].w))));
            }
        }
        // LayerNorm + SiLU per node
        float4 act[4];
#pragma unroll
        for (int j = 0; j < 4; ++j) {
            float s = warp_sum(acc[j].x + acc[j].y + acc[j].z + acc[j].w);
            const float mu = s * (1.0f / HIDDEN);
            const float dx = acc[j].x - mu, dy = acc[j].y - mu;
            const float dz = acc[j].z - mu, dw = acc[j].w - mu;
            float ss = warp_sum(dx * dx + dy * dy + dz * dz + dw * dw);
            const float rstd = rsqrtf(ss * (1.0f / HIDDEN) + LN_EPS);
            act[j].x = silu_f(dx * rstd * gv.x + bev.x);
            act[j].y = silu_f(dy * rstd * gv.y + bev.y);
            act[j].z = silu_f(dz * rstd * gv.z + bev.z);
            act[j].w = silu_f(dw * rstd * gv.w + bev.w);
        }
        // act @ W_upd2 (128 -> 64)
        float o0[4] = {0.f, 0.f, 0.f, 0.f};
        float o1[4] = {0.f, 0.f, 0.f, 0.f};
#pragma unroll
        for (int c = 0; c < 32; ++c) {
            const float2 w0 = *(const float2*)&sW2[(4 * c + 0) * NODE_DIM + lane * 2];
            const float2 w1 = *(const float2*)&sW2[(4 * c + 1) * NODE_DIM + lane * 2];
            const float2 w2 = *(const float2*)&sW2[(4 * c + 2) * NODE_DIM + lane * 2];
            const float2 w3 = *(const float2*)&sW2[(4 * c + 3) * NODE_DIM + lane * 2];
#pragma unroll
            for (int j = 0; j < 4; ++j) {
                const float a0 = __shfl_sync(0xffffffffu, act[j].x, c);
                const float a1 = __shfl_sync(0xffffffffu, act[j].y, c);
                const float a2 = __shfl_sync(0xffffffffu, act[j].z, c);
                const float a3 = __shfl_sync(0xffffffffu, act[j].w, c);
                o0[j] = fmaf(a0, w0.x, fmaf(a1, w1.x, fmaf(a2, w2.x, fmaf(a3, w3.x, o0[j]))));
                o1[j] = fmaf(a0, w0.y, fmaf(a1, w1.y, fmaf(a2, w2.y, fmaf(a3, w3.y, o1[j]))));
            }
        }
#pragma unroll
        for (int j = 0; j < 4; ++j) {
            const int n = base + j;
            if (n < N) {
                float2 res;
                res.x = x0[j] + o0[j] + b2v.x;
                res.y = x1[j] + o1[j] + b2v.y;
                *(float2*)&out[(size_t)n * NODE_DIM + lane * 2] = res;
            }
        }
    }
}

// ---------------- host ----------------
extern "C" void kernel_launch(void* const* d_in, const int* in_sizes, int n_in,
                              void* d_out, int out_size) {
    const float* x      = (const float*)d_in[0];
    const int*   ei     = (const int*)  d_in[1];
    const float* ea     = (const float*)d_in[2];
    const float* Wmsg1  = (const float*)d_in[3];
    const float* bmsg1  = (const float*)d_in[4];
    const float* gmsg   = (const float*)d_in[5];
    const float* bemsg  = (const float*)d_in[6];
    const float* Wmsg2  = (const float*)d_in[7];
    const float* bmsg2  = (const float*)d_in[8];
    const float* Wupd1  = (const float*)d_in[9];
    const float* bupd1  = (const float*)d_in[10];
    const float* gupd   = (const float*)d_in[11];
    const float* beupd  = (const float*)d_in[12];
    const float* Wupd2  = (const float*)d_in[13];
    const float* bupd2  = (const float*)d_in[14];
    float* out = (float*)d_out;

    const int N = in_sizes[0] / NODE_DIM;
    const int E = in_sizes[2] / EDGE_DIM;

    void *pS = nullptr, *pdeg = nullptr;
    cudaGetSymbolAddress(&pS, g_S);
    cudaGetSymbolAddress(&pdeg, g_deg);
    cudaMemsetAsync(pS, 0, (size_t)N * HIDDEN * sizeof(float), 0);
    cudaMemsetAsync(pdeg, 0, (size_t)N * sizeof(float), 0);

    const int smem_proj = HIDDEN * HIDDEN * sizeof(float);                 // 64 KB
    const int smem_upd  = (NODE_DIM * HIDDEN + HIDDEN * HIDDEN +
                           HIDDEN * NODE_DIM + 4 * HIDDEN + NODE_DIM) * sizeof(float); // ~130 KB
    cudaFuncSetAttribute(k_node_proj, cudaFuncAttributeMaxDynamicSharedMemorySize, smem_proj);
    cudaFuncSetAttribute(k_update,    cudaFuncAttributeMaxDynamicSharedMemorySize, smem_upd);

    k_fuse<<<HIDDEN, HIDDEN>>>(Wmsg2, Wupd1, bmsg2);
    k_node_proj<<<296, 256, smem_proj>>>(x, Wmsg1, N);
    k_edge<<<1184, 256>>>(ei, ea, Wmsg1, bmsg1, gmsg, bemsg, E);
    k_update<<<148, 256, smem_upd>>>(x, Wupd1, bupd1, gupd, beupd, Wupd2, bupd2, out, N);
}